// round 12
// baseline (speedup 1.0000x reference)
#include <cuda_runtime.h>
#include <cstdint>

#define S_DIM 2048
#define QT 64
#define KT 128
#define NTHR 256
#define OUT_O_ELEMS 4194304ull
#define KV_ELEMS 4194304

__device__ float    g_inv[65536];          // 1/rowsum per (bh,row)
__device__ uint32_t g_kh[KV_ELEMS / 2];    // K fp16 (half2 words along d)
__device__ uint32_t g_vh[KV_ELEMS / 2];    // V fp16, k-paired

__device__ __forceinline__ uint32_t smem_u32(const void* p) {
  uint32_t a;
  asm("{ .reg .u64 t; cvta.to.shared.u64 t, %1; cvt.u32.u64 %0, t; }" : "=r"(a) : "l"(p));
  return a;
}
__device__ __forceinline__ uint32_t packh2(float lo, float hi) {
  uint32_t r; asm("cvt.rn.f16x2.f32 %0, %1, %2;" : "=r"(r) : "f"(hi), "f"(lo));
  return r;
}
__device__ __forceinline__ void mma16(float c[4], const uint32_t a[4],
                                      uint32_t b0, uint32_t b1) {
  asm volatile("mma.sync.aligned.m16n8k16.row.col.f32.f16.f16.f32 "
    "{%0,%1,%2,%3}, {%4,%5,%6,%7}, {%8,%9}, {%0,%1,%2,%3};"
    : "+f"(c[0]), "+f"(c[1]), "+f"(c[2]), "+f"(c[3])
    : "r"(a[0]), "r"(a[1]), "r"(a[2]), "r"(a[3]), "r"(b0), "r"(b1));
}
#define CP16(dst, src) asm volatile("cp.async.ca.shared.global [%0], [%1], 16;" :: "r"(dst), "l"(src) : "memory")
#define CP_COMMIT()    asm volatile("cp.async.commit_group;" ::: "memory")
#define CP_WAIT0()     asm volatile("cp.async.wait_group 0;" ::: "memory")

// =================== PREP : K,V -> fp16 (V k-paired) ===================
__global__ void __launch_bounds__(256)
kv_prep_kernel(const float* __restrict__ K, const float* __restrict__ V) {
  const int i = blockIdx.x * 256 + threadIdx.x;
  float4 k = ((const float4*)K)[i];
  ((uint2*)g_kh)[i] = make_uint2(packh2(k.x, k.y), packh2(k.z, k.w));
  const int k2g = i >> 5, d2 = i & 31;
  const float2* v0 = (const float2*)(V + (size_t)k2g * 128);
  float2 a = v0[d2], b = v0[32 + d2];
  ((uint2*)g_vh)[(size_t)k2g * 32 + d2] = make_uint2(packh2(a.x, b.x), packh2(a.y, b.y));
}

// ======================= PASS A : row sums (QT=64) =======================
// smem words: Q[64*36=2304] K[2*4608] red[512]
#define A_QW 0
#define A_KW 2304
#define A_RW (A_KW + 9216)
#define A_SMB ((A_RW + 512) * 4)    // 48128 B

__global__ void __launch_bounds__(NTHR, 3)
rowsum_kernel(const float* __restrict__ Q) {
  extern __shared__ __align__(16) uint32_t smw[];
  const uint32_t sb = smem_u32(smw);
  const int tid = threadIdx.x;
  const int w = tid >> 5, lane = tid & 31;
  const int gid = lane >> 2, tg = lane & 3;
  const int bh = blockIdx.y;
  const int qt = (int)gridDim.x - 1 - (int)blockIdx.x;
  const int q0 = qt * QT;

  const float* Qg = Q + ((size_t)bh * S_DIM + q0) * 64;
  const char* Kg = (const char*)g_kh + (size_t)bh * 262144;

  { // stage Q (x 1/8) as fp16: 64 rows x 16 float4
    #pragma unroll
    for (int it = 0; it < 4; ++it) {
      int idx = tid + it * NTHR;
      int r = idx >> 4, f = idx & 15;
      float4 v = ((const float4*)Qg)[idx];
      ((uint2*)(smw + A_QW + r * 36 + 2 * f))[0] =
          make_uint2(packh2(v.x * 0.125f, v.y * 0.125f), packh2(v.z * 0.125f, v.w * 0.125f));
    }
  }
  { // prolog: K tile 0
    #pragma unroll
    for (int it = 0; it < 4; ++it) {
      int idx = tid + it * NTHR;
      int r = idx >> 3, c = idx & 7;
      CP16(sb + A_KW * 4 + r * 144 + c * 16, Kg + r * 128 + c * 16);
    }
    CP_COMMIT();
  }
  __syncthreads();

  const int nkt = (q0 + QT + 127) >> 7;
  float rs[8];
  #pragma unroll
  for (int u = 0; u < 8; ++u) rs[u] = 0.f;

  for (int tt = 0; tt < nkt; ++tt) {
    const int kc = tt << 7;
    CP_WAIT0();
    __syncthreads();
    if (tt + 1 < nkt) {
      const char* kg1 = Kg + (size_t)(kc + KT) * 128;
      uint32_t kd = sb + (A_KW + ((tt + 1) & 1) * 4608) * 4;
      #pragma unroll
      for (int it = 0; it < 4; ++it) {
        int idx = tid + it * NTHR;
        int r = idx >> 3, c = idx & 7;
        CP16(kd + r * 144 + c * 16, kg1 + r * 128 + c * 16);
      }
      CP_COMMIT();
    }
    const uint32_t* kb = smw + A_KW + (tt & 1) * 4608;
    const int nc0 = (16 * w + gid) * 36, nc1 = (16 * w + 8 + gid) * 36;
    const int cg0 = kc + 16 * w + 2 * tg, cg1 = cg0 + 8;

    uint32_t bf[4][4];
    #pragma unroll
    for (int s = 0; s < 4; ++s) {
      bf[s][0] = kb[nc0 + 8 * s + tg];
      bf[s][1] = kb[nc0 + 8 * s + 4 + tg];
      bf[s][2] = kb[nc1 + 8 * s + tg];
      bf[s][3] = kb[nc1 + 8 * s + 4 + tg];
    }

    #pragma unroll
    for (int a = 0; a < 4; ++a) {
      uint32_t af[4][4];
      #pragma unroll
      for (int s = 0; s < 4; ++s) {
        af[s][0] = smw[A_QW + (gid + 16 * a) * 36 + 8 * s + tg];
        af[s][1] = smw[A_QW + (gid + 8 + 16 * a) * 36 + 8 * s + tg];
        af[s][2] = smw[A_QW + (gid + 16 * a) * 36 + 8 * s + 4 + tg];
        af[s][3] = smw[A_QW + (gid + 8 + 16 * a) * 36 + 8 * s + 4 + tg];
      }
      float acc0[4] = {0.f, 0.f, 0.f, 0.f};
      float acc1[4] = {0.f, 0.f, 0.f, 0.f};
      #pragma unroll
      for (int s = 0; s < 4; ++s) {
        mma16(acc0, af[s], bf[s][0], bf[s][1]);
        mma16(acc1, af[s], bf[s][2], bf[s][3]);
      }
      const int ra = q0 + gid + 16 * a, rb = ra + 8;
      rs[2 * a] += ((cg0     <= ra) ? __expf(acc0[0]) : 0.f)
                 + ((cg0 + 1 <= ra) ? __expf(acc0[1]) : 0.f)
                 + ((cg1     <= ra) ? __expf(acc1[0]) : 0.f)
                 + ((cg1 + 1 <= ra) ? __expf(acc1[1]) : 0.f);
      rs[2 * a + 1] += ((cg0     <= rb) ? __expf(acc0[2]) : 0.f)
                     + ((cg0 + 1 <= rb) ? __expf(acc0[3]) : 0.f)
                     + ((cg1     <= rb) ? __expf(acc1[2]) : 0.f)
                     + ((cg1 + 1 <= rb) ? __expf(acc1[3]) : 0.f);
    }
  }

  #pragma unroll
  for (int u = 0; u < 8; ++u) {
    rs[u] += __shfl_xor_sync(~0u, rs[u], 1);
    rs[u] += __shfl_xor_sync(~0u, rs[u], 2);
  }
  float* red = (float*)(smw + A_RW);
  if (tg == 0) {
    #pragma unroll
    for (int a = 0; a < 4; ++a) {
      red[w * 64 + gid + 16 * a]     = rs[2 * a];
      red[w * 64 + gid + 8 + 16 * a] = rs[2 * a + 1];
    }
  }
  __syncthreads();
  if (tid < 64) {
    float s = 0.f;
    #pragma unroll
    for (int i = 0; i < 8; ++i) s += red[i * 64 + tid];
    g_inv[bh * S_DIM + q0 + tid] = 1.0f / s;
  }
}

// ======================= PASS B : W + O (QT=64) =======================
// smem words: Q[2304] K[2*4608] V[2*4352] P[64*68=4352] inv[64]
#define B_QW 0
#define B_KW 2304
#define B_VW (B_KW + 9216)            // 11520
#define B_PW (B_VW + 8704)            // 20224
#define B_IW (B_PW + 4352)            // 24576
#define B_SMB ((B_IW + 64) * 4)       // 98560 B

__global__ void __launch_bounds__(NTHR, 2)
attn_pb_kernel(const float* __restrict__ Q, float* __restrict__ out) {
  extern __shared__ __align__(16) uint32_t smw[];
  const uint32_t sb = smem_u32(smw);
  const int tid = threadIdx.x;
  const int w = tid >> 5, lane = tid & 31;
  const int gid = lane >> 2, tg = lane & 3;
  const int bh = blockIdx.y;
  const int qt = (int)gridDim.x - 1 - (int)blockIdx.x;
  const int q0 = qt * QT;

  const float* Qg = Q + ((size_t)bh * S_DIM + q0) * 64;
  const char* Kg = (const char*)g_kh + (size_t)bh * 262144;
  const char* Vg = (const char*)g_vh + (size_t)bh * 262144;
  float* Og = out + ((size_t)bh * S_DIM + q0) * 64;
  float* Wg = out + OUT_O_ELEMS + ((size_t)bh * S_DIM + q0) * (size_t)S_DIM;

  { // stage Q (x 1/8) as fp16
    #pragma unroll
    for (int it = 0; it < 4; ++it) {
      int idx = tid + it * NTHR;
      int r = idx >> 4, f = idx & 15;
      float4 v = ((const float4*)Qg)[idx];
      ((uint2*)(smw + B_QW + r * 36 + 2 * f))[0] =
          make_uint2(packh2(v.x * 0.125f, v.y * 0.125f), packh2(v.z * 0.125f, v.w * 0.125f));
    }
  }
  if (tid < 64) ((float*)(smw + B_IW))[tid] = g_inv[bh * S_DIM + q0 + tid];
  { // prolog: K + V tile 0
    #pragma unroll
    for (int it = 0; it < 4; ++it) {
      int idx = tid + it * NTHR;
      int r = idx >> 3, c = idx & 7;
      CP16(sb + B_KW * 4 + r * 144 + c * 16, Kg + r * 128 + c * 16);
    }
    #pragma unroll
    for (int it = 0; it < 4; ++it) {
      int idx = tid + it * NTHR;
      int k2 = idx >> 4, c = idx & 15;
      CP16(sb + B_VW * 4 + k2 * 272 + (((c << 2) + 4 * (k2 & 15)) & 63) * 4,
           Vg + k2 * 256 + c * 16);
    }
    CP_COMMIT();
  }
  __syncthreads();

  const int nkt = (q0 + QT + 127) >> 7;
  float oc[8][4];
  #pragma unroll
  for (int j = 0; j < 8; ++j)
    #pragma unroll
    for (int u = 0; u < 4; ++u) oc[j][u] = 0.f;

  // PV role: warp = (atom a2 = w>>1, k64-slice s2 = w&1)
  const int a2 = w >> 1, s2 = w & 1;
  uint32_t* pw = smw + B_PW;
  const float* invs = (const float*)(smw + B_IW);

  for (int tt = 0; tt < nkt; ++tt) {
    const int kc = tt << 7;
    CP_WAIT0();
    __syncthreads();
    if (tt + 1 < nkt) {
      const char* kg1 = Kg + (size_t)(kc + KT) * 128;
      const char* vg1 = Vg + (size_t)(kc >> 1) * 256 + 64 * 256;
      uint32_t kd = sb + (B_KW + ((tt + 1) & 1) * 4608) * 4;
      uint32_t vd = sb + (B_VW + ((tt + 1) & 1) * 4352) * 4;
      #pragma unroll
      for (int it = 0; it < 4; ++it) {
        int idx = tid + it * NTHR;
        int r = idx >> 3, c = idx & 7;
        CP16(kd + r * 144 + c * 16, kg1 + r * 128 + c * 16);
      }
      #pragma unroll
      for (int it = 0; it < 4; ++it) {
        int idx = tid + it * NTHR;
        int k2 = idx >> 4, c = idx & 15;
        CP16(vd + k2 * 272 + (((c << 2) + 4 * (k2 & 15)) & 63) * 4,
             vg1 + k2 * 256 + c * 16);
      }
      CP_COMMIT();
    }
    const uint32_t* kb = smw + B_KW + (tt & 1) * 4608;
    const uint32_t* vb = smw + B_VW + (tt & 1) * 4352;

    // ---- QK: 4 atoms on warp's n16 strip; B-frags hoisted, af reloaded ----
    const int nc0 = (16 * w + gid) * 36, nc1 = (16 * w + 8 + gid) * 36;
    const int cg0 = kc + 16 * w + 2 * tg, cg1 = cg0 + 8;
    const int k2w0 = 8 * w + tg, k2w1 = 8 * w + 4 + tg;

    uint32_t bf[4][4];
    #pragma unroll
    for (int s = 0; s < 4; ++s) {
      bf[s][0] = kb[nc0 + 8 * s + tg];
      bf[s][1] = kb[nc0 + 8 * s + 4 + tg];
      bf[s][2] = kb[nc1 + 8 * s + tg];
      bf[s][3] = kb[nc1 + 8 * s + 4 + tg];
    }

    #pragma unroll
    for (int a = 0; a < 4; ++a) {
      uint32_t af[4][4];
      #pragma unroll
      for (int s = 0; s < 4; ++s) {
        af[s][0] = smw[B_QW + (gid + 16 * a) * 36 + 8 * s + tg];
        af[s][1] = smw[B_QW + (gid + 8 + 16 * a) * 36 + 8 * s + tg];
        af[s][2] = smw[B_QW + (gid + 16 * a) * 36 + 8 * s + 4 + tg];
        af[s][3] = smw[B_QW + (gid + 8 + 16 * a) * 36 + 8 * s + 4 + tg];
      }
      float acc0[4] = {0.f, 0.f, 0.f, 0.f};
      float acc1[4] = {0.f, 0.f, 0.f, 0.f};
      #pragma unroll
      for (int s = 0; s < 4; ++s) {
        mma16(acc0, af[s], bf[s][0], bf[s][1]);
        mma16(acc1, af[s], bf[s][2], bf[s][3]);
      }
      const int ra = q0 + gid + 16 * a, rb = ra + 8;
      const float iva = invs[gid + 16 * a], ivb = invs[gid + 8 + 16 * a];
      float e000 = (cg0     <= ra) ? __expf(acc0[0]) * iva : 0.f;
      float e001 = (cg0 + 1 <= ra) ? __expf(acc0[1]) * iva : 0.f;
      float e010 = (cg0     <= rb) ? __expf(acc0[2]) * ivb : 0.f;
      float e011 = (cg0 + 1 <= rb) ? __expf(acc0[3]) * ivb : 0.f;
      float e100 = (cg1     <= ra) ? __expf(acc1[0]) * iva : 0.f;
      float e101 = (cg1 + 1 <= ra) ? __expf(acc1[1]) * iva : 0.f;
      float e110 = (cg1     <= rb) ? __expf(acc1[2]) * ivb : 0.f;
      float e111 = (cg1 + 1 <= rb) ? __expf(acc1[3]) * ivb : 0.f;
      const int rla = gid + 16 * a, rlb = rla + 8;
      *(float2*)&Wg[(size_t)rla * S_DIM + cg0] = make_float2(e000, e001);
      *(float2*)&Wg[(size_t)rlb * S_DIM + cg0] = make_float2(e010, e011);
      *(float2*)&Wg[(size_t)rla * S_DIM + cg1] = make_float2(e100, e101);
      *(float2*)&Wg[(size_t)rlb * S_DIM + cg1] = make_float2(e110, e111);
      pw[rla * 68 + k2w0] = packh2(e000, e001);
      pw[rlb * 68 + k2w0] = packh2(e010, e011);
      pw[rla * 68 + k2w1] = packh2(e100, e101);
      pw[rlb * 68 + k2w1] = packh2(e110, e111);
    }
    __syncthreads();   // p tile complete before cross-warp PV reads

    // ---- PV: warp (a2, s2): atom a2 rows, k64 slice s2, all 64 d ----
    const int rpa = (gid + 16 * a2) * 68, rpb = (gid + 8 + 16 * a2) * 68;
    #pragma unroll
    for (int c = 0; c < 4; ++c) {
      const int base = 32 * s2 + 8 * c;
      uint32_t pa[4];
      pa[0] = pw[rpa + base + tg];
      pa[1] = pw[rpb + base + tg];
      pa[2] = pw[rpa + base + 4 + tg];
      pa[3] = pw[rpb + base + 4 + tg];
      const int k2a = base + tg, k2b = base + 4 + tg;
      const int swa = 4 * (k2a & 15), swb = 4 * (k2b & 15);
      #pragma unroll
      for (int j = 0; j < 8; ++j) {
        const int d = 8 * j + gid;
        uint32_t b0 = vb[k2a * 68 + ((d + swa) & 63)];
        uint32_t b1 = vb[k2b * 68 + ((d + swb) & 63)];
        mma16(oc[j], pa, b0, b1);
      }
    }
  }

  // ---- W zero tail ----
  {
    const int ktend = nkt * KT;
    const int r = tid >> 2, f = tid & 3;
    float4* wrow = (float4*)(Wg + (size_t)r * S_DIM);
    const float4 z = make_float4(0.f, 0.f, 0.f, 0.f);
    for (int c4 = (ktend >> 2) + f; c4 < (S_DIM >> 2); c4 += 4) wrow[c4] = z;
  }

  // ---- O merge: 2 k-slice partials per atom via smem reuse ----
  __syncthreads();
  float* smf = (float*)smw;
  {
    float* osc = &smf[w * (16 * 66)];
    #pragma unroll
    for (int j = 0; j < 8; ++j) {
      *(float2*)&osc[gid * 66 + j * 8 + 2 * tg]       = make_float2(oc[j][0], oc[j][1]);
      *(float2*)&osc[(gid + 8) * 66 + j * 8 + 2 * tg] = make_float2(oc[j][2], oc[j][3]);
    }
  }
  __syncthreads();
  #pragma unroll
  for (int it = 0; it < 16; ++it) {
    const int e = tid + it * NTHR;
    const int r = e >> 6, d = e & 63;         // r 0..63
    const int wbase = (r >> 4) * 2;           // atom -> warps {wbase, wbase+1}
    const int rl = r & 15;
    float s = smf[wbase * (16 * 66) + rl * 66 + d]
            + smf[(wbase + 1) * (16 * 66) + rl * 66 + d];
    Og[r * 64 + d] = s;
  }
}

extern "C" void kernel_launch(void* const* d_in, const int* in_sizes, int n_in,
                              void* d_out, int out_size) {
  (void)in_sizes; (void)n_in; (void)out_size;
  const float* q = (const float*)d_in[0];
  const float* k = (const float*)d_in[1];
  const float* v = (const float*)d_in[2];
  float* out = (float*)d_out;

  cudaFuncSetAttribute(rowsum_kernel,
                       cudaFuncAttributeMaxDynamicSharedMemorySize, A_SMB);
  cudaFuncSetAttribute(attn_pb_kernel,
                       cudaFuncAttributeMaxDynamicSharedMemorySize, B_SMB);
  dim3 grid(S_DIM / QT, 32);
  kv_prep_kernel<<<KV_ELEMS / 4 / 256, 256>>>(k, v);
  rowsum_kernel<<<grid, NTHR, A_SMB>>>(q);
  attn_pb_kernel<<<grid, NTHR, B_SMB>>>(q, out);
}